// round 16
// baseline (speedup 1.0000x reference)
#include <cuda_runtime.h>
#include <cuda_bf16.h>

// LSTMPolicy via mma.sync.m16n8k8 tf32 SINGLE-PASS (baseline PTX).
// R16: replaces bf16 3-pass hi/lo split -> 2/3 the MMA instructions.
// Weights pre-rounded to tf32 (cvt.rna) in a prep kernel; x and h rounded at use.
// Zero init state => Whh* dead, f-gate dead (c = sigm(i)*tanh(g)).
// Geometry: 512 CTAs x 256 thr; 8 warps = 4 M-pos x 2 N-groups, M=32 rows/warp.

#define BATCH   65536
#define NACT    16
#define TPB     256
#define NBLK    512

// f32(tf32) weight image. Rows padded to 12 words per k8-slice (48B) for
// conflict-free B-fragment LDS.32 (bank = 12g+tg distinct mod 32).
#define L0_CHUNK 18432            // 8 kslices x 48 n x 48B
#define L1_CHUNK 36864            // 16 kslices x 48 n x 48B
#define HD_CHUNK 18432            // 16 kslices x 24 n x 48B
#define OFF_L1   147456
#define OFF_HD   442368
#define WIMG_BYTES 460800

__device__ __align__(16) unsigned char g_wimg[WIMG_BYTES];
__device__ float g_bc0[384];
__device__ float g_bc1[384];
__device__ float g_bch[32];

// smem map (bytes). h rows: 132 words = 528B (bank = 4r+c distinct mod 32).
#define SM_H0   3328
#define SM_H1   70912             // 3328 + 128*528
#define SM_WB   138496            // + 128*528 ; 2 x 36864 weight buffers
#define SMEM_TOTAL 212224

static __device__ __forceinline__ unsigned smem_u32(const void* p) {
    unsigned a;
    asm("{ .reg .u64 t; cvta.to.shared.u64 t, %1; cvt.u32.u64 %0, t; }" : "=r"(a) : "l"(p));
    return a;
}
static __device__ __forceinline__ float tanh_ap(float x) {
    float y; asm("tanh.approx.f32 %0, %1;" : "=f"(y) : "f"(x)); return y;
}
static __device__ __forceinline__ float sigm(float x) {
    return fmaf(0.5f, tanh_ap(0.5f * x), 0.5f);
}
static __device__ __forceinline__ unsigned rna_tf32(float v) {
    unsigned u; asm("cvt.rna.tf32.f32 %0, %1;" : "=r"(u) : "f"(v)); return u;
}

#define LDS32(r, ad) asm volatile("ld.shared.b32 %0, [%1];" : "=r"(r) : "r"(ad))
#define STS32(ad, v) asm volatile("st.shared.b32 [%0], %1;" :: "r"(ad), "r"(v) : "memory")
#define MMA_TF32(c, a, b0, b1) asm volatile( \
    "mma.sync.aligned.m16n8k8.row.col.f32.tf32.tf32.f32 " \
    "{%0,%1,%2,%3}, {%4,%5,%6,%7}, {%8,%9}, {%0,%1,%2,%3};" \
    : "+f"((c)[0]),"+f"((c)[1]),"+f"((c)[2]),"+f"((c)[3]) \
    : "r"((a)[0]),"r"((a)[1]),"r"((a)[2]),"r"((a)[3]), "r"(b0),"r"(b1))

static __device__ __forceinline__ void stage(unsigned sdst, const unsigned char* gsrc,
                                             int granules, int tid) {
    for (int i = tid; i < granules; i += TPB)
        asm volatile("cp.async.cg.shared.global [%0], [%1], 16;"
                     :: "r"(sdst + i * 16), "l"(gsrc + (size_t)i * 16));
    asm volatile("cp.async.commit_group;" ::: "memory");
}

// ======================= weight-prep kernel =======================
__global__ void prep_weights(const float* __restrict__ W0, const float* __restrict__ W1,
                             const float* __restrict__ Wp, const float* __restrict__ Wv,
                             const float* __restrict__ bih0, const float* __restrict__ bhh0,
                             const float* __restrict__ bih1, const float* __restrict__ bhh1,
                             const float* __restrict__ bp,  const float* __restrict__ bv) {
    int id = blockIdx.x * 256 + threadIdx.x;
    if (id < 115200) {                         // one f32 word of the image
        int w = id;
        float v = 0.0f;
        if (w < 36864) {                       // L0: 8 chunks
            int c = w / 4608, q = w % 4608;
            int ks = q / 576; q %= 576;
            int n = q / 12, kw = q % 12;
            if (kw < 8) {
                int gate = n >> 4, j = n & 15;
                int sr = (gate == 0) ? 16*c + j : (gate == 1) ? 256 + 16*c + j : 384 + 16*c + j;
                v = W0[sr * 64 + ks * 8 + kw];
            }
        } else if (w < 110592) {               // L1: 8 chunks
            int i = w - 36864;
            int c = i / 9216, q = i % 9216;
            int ks = q / 576; q %= 576;
            int n = q / 12, kw = q % 12;
            if (kw < 8) {
                int gate = n >> 4, j = n & 15;
                int sr = (gate == 0) ? 16*c + j : (gate == 1) ? 256 + 16*c + j : 384 + 16*c + j;
                v = W1[sr * 128 + ks * 8 + kw];
            }
        } else {                               // heads: 24 n rows [Wp16, Wv, 0x7]
            int i = w - 110592;
            int ks = i / 288, q = i % 288;
            int n = q / 12, kw = q % 12;
            if (kw < 8) {
                int k = ks * 8 + kw;
                v = (n < 16) ? Wp[n * 128 + k] : (n == 16) ? Wv[k] : 0.0f;
            }
        }
        *reinterpret_cast<unsigned*>(g_wimg + (size_t)w * 4) = rna_tf32(v);
    } else if (id < 116000) {
        int i = id - 115200;
        if (i < 384) {
            int gate = i / 128, k = i % 128;
            int sr = (gate == 0) ? k : (gate == 1) ? 256 + k : 384 + k;
            g_bc0[i] = bih0[sr] + bhh0[sr];
        } else if (i < 768) {
            int j = i - 384, gate = j / 128, k = j % 128;
            int sr = (gate == 0) ? k : (gate == 1) ? 256 + k : 384 + k;
            g_bc1[j] = bih1[sr] + bhh1[sr];
        } else if (i < 800) {
            int n = i - 768;
            g_bch[n] = (n < NACT) ? bp[n] : (n == NACT) ? bv[0] : 0.0f;
        }
    }
}

// ======================= main fused kernel =======================
__global__ __launch_bounds__(TPB, 1)
void lstm_mma(const float* __restrict__ x, float* __restrict__ out) {
    extern __shared__ __align__(16) char sm[];
    const unsigned sb = smem_u32(sm);
    const int tid  = threadIdx.x;
    const int warp = tid >> 5, lane = tid & 31;
    const int wm = warp & 3, wg = warp >> 2;        // 4 M-positions x 2 N-groups
    const int g8 = lane >> 2, tg = lane & 3;        // fragment row-group / k-id
    const int kp = tg * 2;                          // accumulator col pair
    float* bias_sm = reinterpret_cast<float*>(sm);

    for (int i = tid; i < 800; i += TPB)
        bias_sm[i] = (i < 384) ? g_bc0[i] : (i < 768) ? g_bc1[i - 384] : g_bch[i - 768];

    stage(sb + SM_WB, g_wimg, L0_CHUNK / 16, tid);  // chunk 0 -> buf 0

    // ---- x fragments: gmem -> tf32-rounded registers. M=32 rows/warp, K=64. ----
    unsigned XR[8][2][4];                           // [kk][m-tile][frag]
    {
        const float* xb = x + ((size_t)blockIdx.x * 128 + 32 * wm + g8) * 64;
        #pragma unroll
        for (int mt = 0; mt < 2; mt++) {
            const float* xr = xb + mt * 16 * 64;
            #pragma unroll
            for (int kk = 0; kk < 8; kk++) {
                int c0 = kk * 8 + tg;
                XR[kk][mt][0] = rna_tf32(__ldg(xr + c0));
                XR[kk][mt][1] = rna_tf32(__ldg(xr + 8 * 64 + c0));
                XR[kk][mt][2] = rna_tf32(__ldg(xr + c0 + 4));
                XR[kk][mt][3] = rna_tf32(__ldg(xr + 8 * 64 + c0 + 4));
            }
        }
    }

    // B-fragment lane offset within an n8 tile row block: n = base + g8, k word = tg
    const unsigned bfrag = (unsigned)g8 * 48 + (unsigned)tg * 4;
    // A-fragment (from h) lane offset: row = base + g8, col word = tg
    const unsigned afrag = (unsigned)g8 * 528 + (unsigned)tg * 4;

    for (int ci = 0; ci < 17; ci++) {
        __syncthreads();                            // all reads of the dst buffer done
        if (ci < 16) {
            int nx = ci + 1;
            unsigned dst = sb + SM_WB + (unsigned)(nx & 1) * 36864;
            const unsigned char* src; int gran;
            if (nx < 8)       { src = g_wimg + nx * L0_CHUNK;             gran = L0_CHUNK / 16; }
            else if (nx < 16) { src = g_wimg + OFF_L1 + (nx-8)*L1_CHUNK;  gran = L1_CHUNK / 16; }
            else              { src = g_wimg + OFF_HD;                    gran = HD_CHUNK / 16; }
            stage(dst, src, gran, tid);
            asm volatile("cp.async.wait_group 1;" ::: "memory");
        } else {
            asm volatile("cp.async.wait_group 0;" ::: "memory");
        }
        __syncthreads();                            // chunk ci visible to all

        const unsigned swb = sb + SM_WB + (unsigned)(ci & 1) * 36864;

        if (ci < 16) {
            const bool l0 = ci < 8;
            const int  c  = l0 ? ci : ci - 8;
            const int  col0 = 16 * c + 8 * wg + kp;
            const float* bs = bias_sm + (l0 ? 0 : 384);
            const unsigned hsrc = sb + SM_H0;       // L1 A source
            const unsigned hdst = sb + (l0 ? SM_H0 : SM_H1);

            float acc[3][2][4];
            #pragma unroll
            for (int g = 0; g < 3; g++) {
                float b0 = bs[g * 128 + col0], b1 = bs[g * 128 + col0 + 1];
                #pragma unroll
                for (int mt = 0; mt < 2; mt++) {
                    acc[g][mt][0] = b0; acc[g][mt][1] = b1;
                    acc[g][mt][2] = b0; acc[g][mt][3] = b1;
                }
            }

            const int nkk = l0 ? 8 : 16;
            #pragma unroll 4
            for (int kk = 0; kk < nkk; kk++) {
                unsigned b[3][2];
                #pragma unroll
                for (int g = 0; g < 3; g++) {
                    unsigned ba = swb + (unsigned)kk * 2304
                                + (unsigned)(g * 16 + 8 * wg) * 48 + bfrag;
                    LDS32(b[g][0], ba);
                    LDS32(b[g][1], ba + 16);
                }
                if (l0) {
                    #pragma unroll
                    for (int g = 0; g < 3; g++) {
                        MMA_TF32(acc[g][0], XR[kk][0], b[g][0], b[g][1]);
                        MMA_TF32(acc[g][1], XR[kk][1], b[g][0], b[g][1]);
                    }
                } else {
                    unsigned ah[2][4];
                    #pragma unroll
                    for (int mt = 0; mt < 2; mt++) {
                        unsigned aa = hsrc + (unsigned)(32*wm + 16*mt) * 528
                                    + (unsigned)kk * 32 + afrag;
                        LDS32(ah[mt][0], aa);
                        LDS32(ah[mt][1], aa + 8 * 528);
                        LDS32(ah[mt][2], aa + 16);
                        LDS32(ah[mt][3], aa + 8 * 528 + 16);
                    }
                    #pragma unroll
                    for (int g = 0; g < 3; g++) {
                        MMA_TF32(acc[g][0], ah[0], b[g][0], b[g][1]);
                        MMA_TF32(acc[g][1], ah[1], b[g][0], b[g][1]);
                    }
                }
            }

            // epilogue: activations -> h (tf32-rounded f32) into h buffer
            #pragma unroll
            for (int mt = 0; mt < 2; mt++)
                #pragma unroll
                for (int q = 0; q < 4; q++) {       // (row-half, col-delta)
                    float iv = acc[0][mt][q], gv = acc[1][mt][q], ov = acc[2][mt][q];
                    float cc = sigm(iv) * tanh_ap(gv);
                    float h  = sigm(ov) * tanh_ap(cc);
                    int row = 32*wm + 16*mt + g8 + 8 * (q >> 1);
                    int col = col0 + (q & 1);
                    STS32(hdst + (unsigned)row * 528 + (unsigned)col * 4, rna_tf32(h));
                }
        } else {
            // heads: A = h1. wg0 -> policy n-tile 0 (+ value tile n=16); wg1 -> tile 8.
            float acc[2][2][4];
            {
                float p0 = bias_sm[768 + 8*wg + kp], p1 = bias_sm[768 + 8*wg + kp + 1];
                float v0 = bias_sm[768 + 16 + kp],   v1 = bias_sm[768 + 16 + kp + 1];
                #pragma unroll
                for (int mt = 0; mt < 2; mt++) {
                    acc[0][mt][0] = p0; acc[0][mt][1] = p1; acc[0][mt][2] = p0; acc[0][mt][3] = p1;
                    acc[1][mt][0] = v0; acc[1][mt][1] = v1; acc[1][mt][2] = v0; acc[1][mt][3] = v1;
                }
            }
            #pragma unroll 4
            for (int kk = 0; kk < 16; kk++) {
                unsigned ah[2][4];
                #pragma unroll
                for (int mt = 0; mt < 2; mt++) {
                    unsigned aa = sb + SM_H1 + (unsigned)(32*wm + 16*mt) * 528
                                + (unsigned)kk * 32 + afrag;
                    LDS32(ah[mt][0], aa);
                    LDS32(ah[mt][1], aa + 8 * 528);
                    LDS32(ah[mt][2], aa + 16);
                    LDS32(ah[mt][3], aa + 8 * 528 + 16);
                }
                unsigned b0, b1, cb0, cb1;
                unsigned ba = swb + (unsigned)kk * 1152 + (unsigned)(8 * wg) * 48 + bfrag;
                LDS32(b0, ba);
                LDS32(b1, ba + 16);
                if (wg == 0) {
                    unsigned ba2 = swb + (unsigned)kk * 1152 + 16u * 48 + bfrag;
                    LDS32(cb0, ba2);
                    LDS32(cb1, ba2 + 16);
                }
                MMA_TF32(acc[0][0], ah[0], b0, b1);
                MMA_TF32(acc[0][1], ah[1], b0, b1);
                if (wg == 0) {
                    MMA_TF32(acc[1][0], ah[0], cb0, cb1);
                    MMA_TF32(acc[1][1], ah[1], cb0, cb1);
                }
            }
            #pragma unroll
            for (int mt = 0; mt < 2; mt++)
                #pragma unroll
                for (int e = 0; e < 2; e++) {
                    size_t r = (size_t)blockIdx.x * 128 + 32*wm + 16*mt + g8 + 8*e;
                    float2 pv = make_float2(acc[0][mt][2*e], acc[0][mt][2*e + 1]);
                    *reinterpret_cast<float2*>(out + r * NACT + 8*wg + kp) = pv;
                    if (wg == 0 && tg == 0)
                        out[(size_t)BATCH * NACT + r] = acc[1][mt][2*e];
                }
        }
    }
}

extern "C" void kernel_launch(void* const* d_in, const int* in_sizes, int n_in,
                              void* d_out, int out_size) {
    const float* x    = (const float*)d_in[0];
    const float* Wih0 = (const float*)d_in[1];
    const float* bih0 = (const float*)d_in[3];
    const float* bhh0 = (const float*)d_in[4];
    const float* Wih1 = (const float*)d_in[5];
    const float* bih1 = (const float*)d_in[7];
    const float* bhh1 = (const float*)d_in[8];
    const float* Wp   = (const float*)d_in[9];
    const float* bp   = (const float*)d_in[10];
    const float* Wv   = (const float*)d_in[11];
    const float* bv   = (const float*)d_in[12];
    float* out = (float*)d_out;

    prep_weights<<<454, 256>>>(Wih0, Wih1, Wp, Wv, bih0, bhh0, bih1, bhh1, bp, bv);

    cudaFuncSetAttribute(lstm_mma, cudaFuncAttributeMaxDynamicSharedMemorySize, SMEM_TOTAL);
    lstm_mma<<<NBLK, TPB, SMEM_TOTAL>>>(x, out);
}